// round 7
// baseline (speedup 1.0000x reference)
#include <cuda_runtime.h>
#include <cuda_bf16.h>
#include <math.h>

#define D 128
#define DV 32          // D / 4 (float4 per row)
#define MAXN 50176
#define MAXE 900032
#define NEG_SLOPE 0.01f

// ---------------- device scratch (no allocations allowed) ----------------
__device__ float g_deg[MAXN];
__device__ float g_dgcn[MAXN];
__device__ float g_dinv[MAXN];
__device__ int   g_rowcnt[MAXN];
__device__ int   g_rowptr[MAXN + 1];
__device__ int   g_rowcur[MAXN];
__device__ int   g_cols[MAXE];
__device__ float g_wts[MAXE];
__device__ float g_bufA[MAXN * D];
__device__ float g_bufB[MAXN * D];
__device__ float g_h[6][MAXN * D];
__device__ float g_W1t[D * D];
__device__ float g_W2t[D * D];

// ---------------- helpers ----------------
__device__ __forceinline__ float lrelu(float v) {
    return v > 0.0f ? v : NEG_SLOPE * v;
}

// ---------------- kernels ----------------
__global__ void init_kernel(float* deg, int* rowcnt, int N) {
    int i = blockIdx.x * blockDim.x + threadIdx.x;
    if (i < N) { deg[i] = 0.0f; rowcnt[i] = 0; }
}

__global__ void deg_kernel(const int* __restrict__ row, const int* __restrict__ col,
                           const float* __restrict__ w, float* deg, int* rowcnt, int E) {
    int e = blockIdx.x * blockDim.x + threadIdx.x;
    if (e < E) {
        atomicAdd(&deg[col[e]], w[e]);
        atomicAdd(&rowcnt[row[e]], 1);
    }
}

__global__ void inv_kernel(const float* __restrict__ deg, float* dgcn, float* dinv, int N) {
    int i = blockIdx.x * blockDim.x + threadIdx.x;
    if (i < N) {
        float d = deg[i];
        dgcn[i] = rsqrtf(d + 1.0f);
        dinv[i] = 1.0f / d;
    }
}

__global__ void scan_kernel(const int* __restrict__ cnt, int* ptr, int* cur, int N) {
    __shared__ int ssum[1024];
    int tid = threadIdx.x;
    int C = (N + 1023) / 1024;
    int b0 = tid * C;
    int b1 = b0 + C; if (b1 > N) b1 = N; if (b0 > N) b0 = N;
    int s = 0;
    for (int i = b0; i < b1; i++) s += cnt[i];
    ssum[tid] = s;
    __syncthreads();
    for (int off = 1; off < 1024; off <<= 1) {
        int v = (tid >= off) ? ssum[tid - off] : 0;
        __syncthreads();
        ssum[tid] += v;
        __syncthreads();
    }
    int run = (tid == 0) ? 0 : ssum[tid - 1];
    for (int i = b0; i < b1; i++) {
        ptr[i] = run; cur[i] = run;
        run += cnt[i];
    }
    if (tid == 1023) ptr[N] = ssum[1023];
}

__global__ void build_kernel(const int* __restrict__ row, const int* __restrict__ col,
                             const float* __restrict__ w, int* cur,
                             int* cols, float* wts, int E) {
    int e = blockIdx.x * blockDim.x + threadIdx.x;
    if (e < E) {
        int pos = atomicAdd(&cur[row[e]], 1);
        cols[pos] = col[e];
        wts[pos]  = w[e];
    }
}

__global__ void transpose_kernel(const float* __restrict__ W, float* Wt) {
    int idx = blockIdx.x * blockDim.x + threadIdx.x;  // idx = d*128 + j
    if (idx < D * D) {
        int d = idx >> 7, j = idx & 127;
        Wt[idx] = W[j * D + d];
    }
}

// GCN step: out = (spmm(x*dg) + x*dg) * dg ; hout = leaky(out); optional xout = out.
__global__ void gcn_kernel(const float4* __restrict__ xin, float4* xout, float4* hout,
                           const float* __restrict__ dg, const int* __restrict__ rp,
                           const int* __restrict__ cols, const float* __restrict__ wts,
                           int N) {
    int warp = (blockIdx.x * blockDim.x + threadIdx.x) >> 5;
    int lane = threadIdx.x & 31;
    if (warp >= N) return;
    int beg = rp[warp], end = rp[warp + 1];
    float4 acc = make_float4(0.f, 0.f, 0.f, 0.f);
    for (int e = beg; e < end; e++) {
        int c = cols[e];
        float s = wts[e] * dg[c];
        float4 v = xin[c * DV + lane];
        acc.x += s * v.x; acc.y += s * v.y; acc.z += s * v.z; acc.w += s * v.w;
    }
    float dr = dg[warp];
    float4 xr = xin[warp * DV + lane];
    float4 val;
    val.x = (acc.x + xr.x * dr) * dr;
    val.y = (acc.y + xr.y * dr) * dr;
    val.z = (acc.z + xr.z * dr) * dr;
    val.w = (acc.w + xr.w * dr) * dr;
    if (xout) xout[warp * DV + lane] = val;
    float4 h;
    h.x = lrelu(val.x); h.y = lrelu(val.y); h.z = lrelu(val.z); h.w = lrelu(val.w);
    hout[warp * DV + lane] = h;
}

// Scatter step: new = 0.5*fp + 0.5*spmm(dinv*fp); optional fpout=new; optional hs=|fp-new|^m
__global__ void scat_kernel(const float4* __restrict__ fpin, float4* fpout, float4* hsout,
                            const float* __restrict__ dinv, const int* __restrict__ rp,
                            const int* __restrict__ cols, const float* __restrict__ wts,
                            const int* __restrict__ moment, int N) {
    int warp = (blockIdx.x * blockDim.x + threadIdx.x) >> 5;
    int lane = threadIdx.x & 31;
    if (warp >= N) return;
    int beg = rp[warp], end = rp[warp + 1];
    float4 acc = make_float4(0.f, 0.f, 0.f, 0.f);
    for (int e = beg; e < end; e++) {
        int c = cols[e];
        float s = wts[e] * dinv[c];
        float4 v = fpin[c * DV + lane];
        acc.x += s * v.x; acc.y += s * v.y; acc.z += s * v.z; acc.w += s * v.w;
    }
    float4 fr = fpin[warp * DV + lane];
    float4 nv;
    nv.x = 0.5f * fr.x + 0.5f * acc.x;
    nv.y = 0.5f * fr.y + 0.5f * acc.y;
    nv.z = 0.5f * fr.z + 0.5f * acc.z;
    nv.w = 0.5f * fr.w + 0.5f * acc.w;
    if (fpout) fpout[warp * DV + lane] = nv;
    if (hsout) {
        int m = moment[0];
        float4 hs;
        hs.x = fabsf(fr.x - nv.x); hs.y = fabsf(fr.y - nv.y);
        hs.z = fabsf(fr.z - nv.z); hs.w = fabsf(fr.w - nv.w);
        if (m != 1) {
            float fm = (float)m;
            hs.x = powf(hs.x, fm); hs.y = powf(hs.y, fm);
            hs.z = powf(hs.z, fm); hs.w = powf(hs.w, fm);
        }
        hsout[warp * DV + lane] = hs;
    }
}

// Attention: e_c = sum_d relu(h_c[n,d])*a[D+d]; softmax over c; hp = (1/6) sum attn_c * h_c
__global__ void attn_kernel(const float* __restrict__ hbase, long hstride,
                            const float* __restrict__ a, float4* __restrict__ hp, int N) {
    int node = (blockIdx.x * blockDim.x + threadIdx.x) >> 5;
    int lane = threadIdx.x & 31;
    if (node >= N) return;
    float4 av = ((const float4*)a)[DV + lane];   // a[D + lane*4 .. +3]
    float4 vals[6];
    float ec[6];
#pragma unroll
    for (int c = 0; c < 6; c++) {
        const float4* h = (const float4*)(hbase + (long)c * hstride);
        float4 v = h[node * DV + lane];
        vals[c] = v;
        float p = fmaxf(v.x, 0.f) * av.x + fmaxf(v.y, 0.f) * av.y +
                  fmaxf(v.z, 0.f) * av.z + fmaxf(v.w, 0.f) * av.w;
#pragma unroll
        for (int off = 16; off > 0; off >>= 1)
            p += __shfl_xor_sync(0xffffffffu, p, off);
        ec[c] = p;
    }
    float mx = ec[0];
#pragma unroll
    for (int c = 1; c < 6; c++) mx = fmaxf(mx, ec[c]);
    float s = 0.f;
    float w[6];
#pragma unroll
    for (int c = 0; c < 6; c++) { w[c] = __expf(ec[c] - mx); s += w[c]; }
    float inv = 1.0f / (6.0f * s);
    float4 o = make_float4(0.f, 0.f, 0.f, 0.f);
#pragma unroll
    for (int c = 0; c < 6; c++) {
        float ww = w[c] * inv;
        o.x += ww * vals[c].x; o.y += ww * vals[c].y;
        o.z += ww * vals[c].z; o.w += ww * vals[c].w;
    }
    hp[node * DV + lane] = o;
}

// out[n,j] = leaky( sum_d in[n,d]*Wt[d,j] + b[j] ).  Wt is (D,D) with Wt[d*128+j] = W[j,d].
// Block: 256 threads, 64 rows x 128 cols; thread = 4 rows x 8 cols.
__global__ void gemm_kernel(const float* __restrict__ in, const float* __restrict__ Wt,
                            const float* __restrict__ b, float* __restrict__ out, int N) {
    __shared__ float sH[64][16];
    __shared__ float sW[16][D];
    int tid = threadIdx.x;
    int base = blockIdx.x * 64;
    int tx = tid & 15;          // col group
    int ty = tid >> 4;          // row group
    int j0 = tx * 8;
    int r0 = ty * 4;
    float acc[4][8];
#pragma unroll
    for (int i = 0; i < 4; i++)
#pragma unroll
        for (int j = 0; j < 8; j++) acc[i][j] = 0.f;

    for (int k0 = 0; k0 < D; k0 += 16) {
        // load H tile: 64x16 = 256 float4
        {
            int r = tid >> 2;          // 0..63
            int kq = tid & 3;          // 0..3
            float4 v = make_float4(0.f, 0.f, 0.f, 0.f);
            if (base + r < N)
                v = *(const float4*)&in[(long)(base + r) * D + k0 + kq * 4];
            *(float4*)&sH[r][kq * 4] = v;
        }
        // load W tile: 16x128 = 512 float4, 2 per thread
        {
#pragma unroll
            for (int p = 0; p < 2; p++) {
                int f = tid + p * 256;     // 0..511
                int kk = f >> 5;           // 0..15
                int j4 = f & 31;           // 0..31
                *(float4*)&sW[kk][j4 * 4] =
                    *(const float4*)&Wt[(long)(k0 + kk) * D + j4 * 4];
            }
        }
        __syncthreads();
#pragma unroll
        for (int kk = 0; kk < 16; kk++) {
            float h0 = sH[r0 + 0][kk];
            float h1 = sH[r0 + 1][kk];
            float h2 = sH[r0 + 2][kk];
            float h3 = sH[r0 + 3][kk];
            float4 w0 = *(float4*)&sW[kk][j0];
            float4 w1 = *(float4*)&sW[kk][j0 + 4];
            float wv[8] = {w0.x, w0.y, w0.z, w0.w, w1.x, w1.y, w1.z, w1.w};
#pragma unroll
            for (int j = 0; j < 8; j++) {
                acc[0][j] += h0 * wv[j];
                acc[1][j] += h1 * wv[j];
                acc[2][j] += h2 * wv[j];
                acc[3][j] += h3 * wv[j];
            }
        }
        __syncthreads();
    }
    float bb[8];
#pragma unroll
    for (int j = 0; j < 8; j++) bb[j] = b[j0 + j];
#pragma unroll
    for (int i = 0; i < 4; i++) {
        int r = base + r0 + i;
        if (r < N) {
            float4 o0, o1;
            float v;
            v = acc[i][0] + bb[0]; o0.x = lrelu(v);
            v = acc[i][1] + bb[1]; o0.y = lrelu(v);
            v = acc[i][2] + bb[2]; o0.z = lrelu(v);
            v = acc[i][3] + bb[3]; o0.w = lrelu(v);
            v = acc[i][4] + bb[4]; o1.x = lrelu(v);
            v = acc[i][5] + bb[5]; o1.y = lrelu(v);
            v = acc[i][6] + bb[6]; o1.z = lrelu(v);
            v = acc[i][7] + bb[7]; o1.w = lrelu(v);
            *(float4*)&out[(long)r * D + j0] = o0;
            *(float4*)&out[(long)r * D + j0 + 4] = o1;
        }
    }
}

// ---------------- host launch ----------------
extern "C" void kernel_launch(void* const* d_in, const int* in_sizes, int n_in,
                              void* d_out, int out_size) {
    const float* X   = (const float*)d_in[0];
    const int*   ei  = (const int*)d_in[1];
    const float* w   = (const float*)d_in[2];
    const float* W1  = (const float*)d_in[3];
    const float* b1  = (const float*)d_in[4];
    const float* W2  = (const float*)d_in[5];
    const float* b2  = (const float*)d_in[6];
    const float* a   = (const float*)d_in[7];
    const int*   mom = (const int*)d_in[8];

    int N = in_sizes[0] / D;
    int E = in_sizes[1] / 2;
    const int* row = ei;
    const int* col = ei + E;

    // resolve device scratch symbols
    float *deg, *dgcn, *dinv, *bufA, *bufB, *hbase, *W1t, *W2t, *wts;
    int *rowcnt, *rowptr, *rowcur, *cols;
    cudaGetSymbolAddress((void**)&deg, g_deg);
    cudaGetSymbolAddress((void**)&dgcn, g_dgcn);
    cudaGetSymbolAddress((void**)&dinv, g_dinv);
    cudaGetSymbolAddress((void**)&rowcnt, g_rowcnt);
    cudaGetSymbolAddress((void**)&rowptr, g_rowptr);
    cudaGetSymbolAddress((void**)&rowcur, g_rowcur);
    cudaGetSymbolAddress((void**)&cols, g_cols);
    cudaGetSymbolAddress((void**)&wts, g_wts);
    cudaGetSymbolAddress((void**)&bufA, g_bufA);
    cudaGetSymbolAddress((void**)&bufB, g_bufB);
    cudaGetSymbolAddress((void**)&hbase, g_h);
    cudaGetSymbolAddress((void**)&W1t, g_W1t);
    cudaGetSymbolAddress((void**)&W2t, g_W2t);
    const long HS = (long)MAXN * D;

    int nb = (N + 255) / 256;
    int eb = (E + 255) / 256;
    int wb = (N + 7) / 8;          // warp-per-row blocks (256 thr = 8 warps)

    init_kernel<<<nb, 256>>>(deg, rowcnt, N);
    deg_kernel<<<eb, 256>>>(row, col, w, deg, rowcnt, E);
    inv_kernel<<<nb, 256>>>(deg, dgcn, dinv, N);
    scan_kernel<<<1, 1024>>>(rowcnt, rowptr, rowcur, N);
    build_kernel<<<eb, 256>>>(row, col, w, rowcur, cols, wts, E);
    transpose_kernel<<<64, 256>>>(W1, W1t);
    transpose_kernel<<<64, 256>>>(W2, W2t);

    // GCN: 3 iterations -> h[0..2]
    gcn_kernel<<<wb, 256>>>((const float4*)X,    (float4*)bufA, (float4*)(hbase + 0 * HS),
                            dgcn, rowptr, cols, wts, N);
    gcn_kernel<<<wb, 256>>>((const float4*)bufA, (float4*)bufB, (float4*)(hbase + 1 * HS),
                            dgcn, rowptr, cols, wts, N);
    gcn_kernel<<<wb, 256>>>((const float4*)bufB, nullptr,       (float4*)(hbase + 2 * HS),
                            dgcn, rowptr, cols, wts, N);

    // Scattering: 4 iterations -> h[3..5]
    scat_kernel<<<wb, 256>>>((const float4*)X,    (float4*)bufA, nullptr,
                             dinv, rowptr, cols, wts, mom, N);
    scat_kernel<<<wb, 256>>>((const float4*)bufA, (float4*)bufB, (float4*)(hbase + 3 * HS),
                             dinv, rowptr, cols, wts, mom, N);
    scat_kernel<<<wb, 256>>>((const float4*)bufB, (float4*)bufA, (float4*)(hbase + 4 * HS),
                             dinv, rowptr, cols, wts, mom, N);
    scat_kernel<<<wb, 256>>>((const float4*)bufA, nullptr,       (float4*)(hbase + 5 * HS),
                             dinv, rowptr, cols, wts, mom, N);

    // Attention -> h_prime in bufB
    attn_kernel<<<wb, 256>>>(hbase, HS, a, (float4*)bufB, N);

    // Output MLP
    int gb = (N + 63) / 64;
    gemm_kernel<<<gb, 256>>>(bufB, W1t, b1, bufA, N);
    gemm_kernel<<<gb, 256>>>(bufA, W2t, b2, (float*)d_out, N);
}

// round 9
// speedup vs baseline: 1.2485x; 1.2485x over previous
#include <cuda_runtime.h>
#include <cuda_bf16.h>
#include <math.h>

#define D 128
#define DV 32          // D / 4 (float4 per row)
#define MAXN 50176
#define MAXE 900032
#define NEG_SLOPE 0.01f

// ---------------- device scratch (no allocations allowed) ----------------
__device__ float g_deg[MAXN];
__device__ float g_dgcn[MAXN];
__device__ float g_dinv[MAXN];
__device__ int   g_rowcnt[MAXN];
__device__ int   g_rowptr[MAXN + 1];
__device__ int   g_rowcur[MAXN];
__device__ int   g_bsum[256];
__device__ int2  g_eg[MAXE];   // (col, w * dgcn[col])
__device__ int2  g_ei[MAXE];   // (col, w * dinv[col])
__device__ float g_bufA[MAXN * D];   // fp4
__device__ float g_bufB[MAXN * D];   // h_prime
__device__ float g_h[6][MAXN * D];   // v1,v2,v3, fp1,fp2,fp3 (g_h[0] reused as inter)
__device__ float g_W1t[D * D];
__device__ float g_W2t[D * D];

// ---------------- helpers ----------------
__device__ __forceinline__ float lrelu(float v) {
    return v > 0.0f ? v : NEG_SLOPE * v;
}
__device__ __forceinline__ void ffma2(unsigned long long& acc,
                                      unsigned long long a, unsigned long long b) {
    asm("fma.rn.f32x2 %0, %1, %2, %0;" : "+l"(acc) : "l"(a), "l"(b));
}
__device__ __forceinline__ unsigned long long pack2(float v) {
    unsigned long long r;
    asm("mov.b64 %0, {%1, %1};" : "=l"(r) : "f"(v));
    return r;
}
__device__ __forceinline__ void unpack2(unsigned long long p, float& lo, float& hi) {
    asm("mov.b64 {%0, %1}, %2;" : "=f"(lo), "=f"(hi) : "l"(p));
}

// ---------------- setup kernels ----------------
__global__ void init_kernel(float* deg, int* rowcnt, int N) {
    int i = blockIdx.x * blockDim.x + threadIdx.x;
    if (i < N) { deg[i] = 0.0f; rowcnt[i] = 0; }
}

__global__ void deg_kernel(const int* __restrict__ row, const int* __restrict__ col,
                           const float* __restrict__ w, float* deg, int* rowcnt, int E) {
    int e = blockIdx.x * blockDim.x + threadIdx.x;
    if (e < E) {
        atomicAdd(&deg[col[e]], w[e]);
        atomicAdd(&rowcnt[row[e]], 1);
    }
}

__global__ void inv_kernel(const float* __restrict__ deg, float* dgcn, float* dinv, int N) {
    int i = blockIdx.x * blockDim.x + threadIdx.x;
    if (i < N) {
        float d = deg[i];
        dgcn[i] = rsqrtf(d + 1.0f);
        dinv[i] = 1.0f / d;
    }
}

// --- parallel scan: A) per-block sums, B) scan sums, C) per-block scan + offset ---
__global__ void scanA_kernel(const int* __restrict__ cnt, int* bsum, int N) {
    __shared__ int sm[8];
    int tid = threadIdx.x;
    int i = blockIdx.x * 256 + tid;
    int v = (i < N) ? cnt[i] : 0;
#pragma unroll
    for (int off = 16; off > 0; off >>= 1) v += __shfl_xor_sync(0xffffffffu, v, off);
    if ((tid & 31) == 0) sm[tid >> 5] = v;
    __syncthreads();
    if (tid == 0) {
        int s = 0;
#pragma unroll
        for (int k = 0; k < 8; k++) s += sm[k];
        bsum[blockIdx.x] = s;
    }
}

__global__ void scanB_kernel(int* bsum, int nb) {
    __shared__ int s[256];
    int tid = threadIdx.x;
    int v = (tid < nb) ? bsum[tid] : 0;
    s[tid] = v;
    __syncthreads();
#pragma unroll
    for (int off = 1; off < 256; off <<= 1) {
        int t = (tid >= off) ? s[tid - off] : 0;
        __syncthreads();
        s[tid] += t;
        __syncthreads();
    }
    if (tid < nb) bsum[tid] = s[tid] - v;   // exclusive
}

__global__ void scanC_kernel(const int* __restrict__ cnt, const int* __restrict__ boff,
                             int* ptr, int* cur, int N, int E) {
    __shared__ int s[256];
    int tid = threadIdx.x;
    int i = blockIdx.x * 256 + tid;
    int v = (i < N) ? cnt[i] : 0;
    s[tid] = v;
    __syncthreads();
#pragma unroll
    for (int off = 1; off < 256; off <<= 1) {
        int t = (tid >= off) ? s[tid - off] : 0;
        __syncthreads();
        s[tid] += t;
        __syncthreads();
    }
    int ex = s[tid] - v + boff[blockIdx.x];
    if (i < N) { ptr[i] = ex; cur[i] = ex; }
    if (i == 0) ptr[N] = E;
}

__global__ void build_kernel(const int* __restrict__ row, const int* __restrict__ col,
                             const float* __restrict__ w,
                             const float* __restrict__ dgcn, const float* __restrict__ dinv,
                             int* cur, int2* eg, int2* ei, int E) {
    int e = blockIdx.x * blockDim.x + threadIdx.x;
    if (e < E) {
        int r = row[e], c = col[e];
        float ww = w[e];
        int pos = atomicAdd(&cur[r], 1);
        eg[pos] = make_int2(c, __float_as_int(ww * dgcn[c]));
        ei[pos] = make_int2(c, __float_as_int(ww * dinv[c]));
    }
}

__global__ void transpose_kernel(const float* __restrict__ W, float* Wt) {
    int idx = blockIdx.x * blockDim.x + threadIdx.x;  // idx = d*128 + j
    if (idx < D * D) {
        int d = idx >> 7, j = idx & 127;
        Wt[idx] = W[j * D + d];
    }
}

// ---------------- SpMM kernels (warp per row, unroll-4) ----------------
// GCN step: vout = (spmm_{w*dg[col]}(x) + x*dg) * dg   (raw val; leaky applied in attn)
__global__ void gcn_kernel(const float4* __restrict__ xin, float4* __restrict__ vout,
                           const float* __restrict__ dg, const int* __restrict__ rp,
                           const int2* __restrict__ ed, int N) {
    int warp = (blockIdx.x * blockDim.x + threadIdx.x) >> 5;
    int lane = threadIdx.x & 31;
    if (warp >= N) return;
    int beg = rp[warp], end = rp[warp + 1];
    float4 acc = make_float4(0.f, 0.f, 0.f, 0.f);
    int e = beg;
    for (; e + 4 <= end; e += 4) {
        int2 p0 = ed[e], p1 = ed[e + 1], p2 = ed[e + 2], p3 = ed[e + 3];
        float4 v0 = xin[p0.x * DV + lane];
        float4 v1 = xin[p1.x * DV + lane];
        float4 v2 = xin[p2.x * DV + lane];
        float4 v3 = xin[p3.x * DV + lane];
        float s0 = __int_as_float(p0.y), s1 = __int_as_float(p1.y);
        float s2 = __int_as_float(p2.y), s3 = __int_as_float(p3.y);
        acc.x += s0 * v0.x + s1 * v1.x + s2 * v2.x + s3 * v3.x;
        acc.y += s0 * v0.y + s1 * v1.y + s2 * v2.y + s3 * v3.y;
        acc.z += s0 * v0.z + s1 * v1.z + s2 * v2.z + s3 * v3.z;
        acc.w += s0 * v0.w + s1 * v1.w + s2 * v2.w + s3 * v3.w;
    }
    for (; e < end; e++) {
        int2 p = ed[e];
        float s = __int_as_float(p.y);
        float4 v = xin[p.x * DV + lane];
        acc.x += s * v.x; acc.y += s * v.y; acc.z += s * v.z; acc.w += s * v.w;
    }
    float dr = dg[warp];
    float4 xr = xin[warp * DV + lane];
    float4 val;
    val.x = (acc.x + xr.x * dr) * dr;
    val.y = (acc.y + xr.y * dr) * dr;
    val.z = (acc.z + xr.z * dr) * dr;
    val.w = (acc.w + xr.w * dr) * dr;
    vout[warp * DV + lane] = val;
}

// Scatter step: fpout = 0.5*fp + 0.5*spmm_{w*dinv[col]}(fp)
__global__ void scat_kernel(const float4* __restrict__ fpin, float4* __restrict__ fpout,
                            const int* __restrict__ rp, const int2* __restrict__ ed, int N) {
    int warp = (blockIdx.x * blockDim.x + threadIdx.x) >> 5;
    int lane = threadIdx.x & 31;
    if (warp >= N) return;
    int beg = rp[warp], end = rp[warp + 1];
    float4 acc = make_float4(0.f, 0.f, 0.f, 0.f);
    int e = beg;
    for (; e + 4 <= end; e += 4) {
        int2 p0 = ed[e], p1 = ed[e + 1], p2 = ed[e + 2], p3 = ed[e + 3];
        float4 v0 = fpin[p0.x * DV + lane];
        float4 v1 = fpin[p1.x * DV + lane];
        float4 v2 = fpin[p2.x * DV + lane];
        float4 v3 = fpin[p3.x * DV + lane];
        float s0 = __int_as_float(p0.y), s1 = __int_as_float(p1.y);
        float s2 = __int_as_float(p2.y), s3 = __int_as_float(p3.y);
        acc.x += s0 * v0.x + s1 * v1.x + s2 * v2.x + s3 * v3.x;
        acc.y += s0 * v0.y + s1 * v1.y + s2 * v2.y + s3 * v3.y;
        acc.z += s0 * v0.z + s1 * v1.z + s2 * v2.z + s3 * v3.z;
        acc.w += s0 * v0.w + s1 * v1.w + s2 * v2.w + s3 * v3.w;
    }
    for (; e < end; e++) {
        int2 p = ed[e];
        float s = __int_as_float(p.y);
        float4 v = fpin[p.x * DV + lane];
        acc.x += s * v.x; acc.y += s * v.y; acc.z += s * v.z; acc.w += s * v.w;
    }
    float4 fr = fpin[warp * DV + lane];
    float4 nv;
    nv.x = 0.5f * fr.x + 0.5f * acc.x;
    nv.y = 0.5f * fr.y + 0.5f * acc.y;
    nv.z = 0.5f * fr.z + 0.5f * acc.z;
    nv.w = 0.5f * fr.w + 0.5f * acc.w;
    fpout[warp * DV + lane] = nv;
}

// ---------------- attention (reads raw channels, applies leaky / |diff|^m) ----------------
__global__ void attn_kernel(const float4* __restrict__ v1, const float4* __restrict__ v2,
                            const float4* __restrict__ v3, const float4* __restrict__ f1,
                            const float4* __restrict__ f2, const float4* __restrict__ f3,
                            const float4* __restrict__ f4,
                            const float* __restrict__ a, const int* __restrict__ moment,
                            float4* __restrict__ hp, int N) {
    int node = (blockIdx.x * blockDim.x + threadIdx.x) >> 5;
    int lane = threadIdx.x & 31;
    if (node >= N) return;
    long idx = (long)node * DV + lane;
    float4 av = ((const float4*)a)[DV + lane];   // a[D + lane*4 .. +3]

    float4 vals[6];
    {
        float4 t;
        t = v1[idx];
        vals[0] = make_float4(lrelu(t.x), lrelu(t.y), lrelu(t.z), lrelu(t.w));
        t = v2[idx];
        vals[1] = make_float4(lrelu(t.x), lrelu(t.y), lrelu(t.z), lrelu(t.w));
        t = v3[idx];
        vals[2] = make_float4(lrelu(t.x), lrelu(t.y), lrelu(t.z), lrelu(t.w));
        float4 a1 = f1[idx], a2 = f2[idx], a3 = f3[idx], a4 = f4[idx];
        vals[3] = make_float4(fabsf(a1.x - a2.x), fabsf(a1.y - a2.y),
                              fabsf(a1.z - a2.z), fabsf(a1.w - a2.w));
        vals[4] = make_float4(fabsf(a2.x - a3.x), fabsf(a2.y - a3.y),
                              fabsf(a2.z - a3.z), fabsf(a2.w - a3.w));
        vals[5] = make_float4(fabsf(a3.x - a4.x), fabsf(a3.y - a4.y),
                              fabsf(a3.z - a4.z), fabsf(a3.w - a4.w));
        int m = moment[0];
        if (m != 1) {
            float fm = (float)m;
#pragma unroll
            for (int c = 3; c < 6; c++) {
                vals[c].x = powf(vals[c].x, fm); vals[c].y = powf(vals[c].y, fm);
                vals[c].z = powf(vals[c].z, fm); vals[c].w = powf(vals[c].w, fm);
            }
        }
    }
    float ec[6];
#pragma unroll
    for (int c = 0; c < 6; c++) {
        float4 v = vals[c];
        float p = fmaxf(v.x, 0.f) * av.x + fmaxf(v.y, 0.f) * av.y +
                  fmaxf(v.z, 0.f) * av.z + fmaxf(v.w, 0.f) * av.w;
#pragma unroll
        for (int off = 16; off > 0; off >>= 1)
            p += __shfl_xor_sync(0xffffffffu, p, off);
        ec[c] = p;
    }
    float mx = ec[0];
#pragma unroll
    for (int c = 1; c < 6; c++) mx = fmaxf(mx, ec[c]);
    float s = 0.f;
    float w[6];
#pragma unroll
    for (int c = 0; c < 6; c++) { w[c] = __expf(ec[c] - mx); s += w[c]; }
    float inv = 1.0f / (6.0f * s);
    float4 o = make_float4(0.f, 0.f, 0.f, 0.f);
#pragma unroll
    for (int c = 0; c < 6; c++) {
        float ww = w[c] * inv;
        o.x += ww * vals[c].x; o.y += ww * vals[c].y;
        o.z += ww * vals[c].z; o.w += ww * vals[c].w;
    }
    hp[idx] = o;
}

// ---------------- GEMM with packed f32x2 FMA ----------------
// out[n,j] = leaky( sum_d in[n,d]*Wt[d,j] + b[j] ).  Wt[d*128+j] = W[j,d].
// Block: 256 threads, 64 rows x 128 cols; thread = 4 rows x 8 cols (4 f32x2 pairs).
__global__ void gemm_kernel(const float* __restrict__ in, const float* __restrict__ Wt,
                            const float* __restrict__ b, float* __restrict__ out, int N) {
    __shared__ __align__(16) float sH[64][16];
    __shared__ __align__(16) float sW[16][D];
    int tid = threadIdx.x;
    int base = blockIdx.x * 64;
    int tx = tid & 15;          // col group (8 cols = 4 pairs)
    int ty = tid >> 4;          // row group (4 rows)
    int j0 = tx * 8;
    int r0 = ty * 4;
    unsigned long long acc[4][4];
#pragma unroll
    for (int i = 0; i < 4; i++)
#pragma unroll
        for (int p = 0; p < 4; p++) acc[i][p] = 0ULL;

    for (int k0 = 0; k0 < D; k0 += 16) {
        // load H tile: 64x16 = 256 float4
        {
            int r = tid >> 2;          // 0..63
            int kq = tid & 3;          // 0..3
            float4 v = make_float4(0.f, 0.f, 0.f, 0.f);
            if (base + r < N)
                v = *(const float4*)&in[(long)(base + r) * D + k0 + kq * 4];
            *(float4*)&sH[r][kq * 4] = v;
        }
        // load W tile: 16x128 = 512 float4, 2 per thread
        {
#pragma unroll
            for (int p = 0; p < 2; p++) {
                int f = tid + p * 256;     // 0..511
                int kk = f >> 5;           // 0..15
                int j4 = f & 31;           // 0..31
                *(float4*)&sW[kk][j4 * 4] =
                    *(const float4*)&Wt[(long)(k0 + kk) * D + j4 * 4];
            }
        }
        __syncthreads();
#pragma unroll
        for (int kk = 0; kk < 16; kk++) {
            const unsigned long long* wp =
                (const unsigned long long*)&sW[kk][j0];
            unsigned long long w0 = wp[0], w1 = wp[1], w2 = wp[2], w3 = wp[3];
#pragma unroll
            for (int i = 0; i < 4; i++) {
                unsigned long long hh = pack2(sH[r0 + i][kk]);
                ffma2(acc[i][0], hh, w0);
                ffma2(acc[i][1], hh, w1);
                ffma2(acc[i][2], hh, w2);
                ffma2(acc[i][3], hh, w3);
            }
        }
        __syncthreads();
    }
    float bb[8];
#pragma unroll
    for (int j = 0; j < 8; j++) bb[j] = b[j0 + j];
#pragma unroll
    for (int i = 0; i < 4; i++) {
        int r = base + r0 + i;
        if (r < N) {
            float res[8];
#pragma unroll
            for (int p = 0; p < 4; p++)
                unpack2(acc[i][p], res[2 * p], res[2 * p + 1]);
            float4 o0, o1;
            o0.x = lrelu(res[0] + bb[0]); o0.y = lrelu(res[1] + bb[1]);
            o0.z = lrelu(res[2] + bb[2]); o0.w = lrelu(res[3] + bb[3]);
            o1.x = lrelu(res[4] + bb[4]); o1.y = lrelu(res[5] + bb[5]);
            o1.z = lrelu(res[6] + bb[6]); o1.w = lrelu(res[7] + bb[7]);
            *(float4*)&out[(long)r * D + j0] = o0;
            *(float4*)&out[(long)r * D + j0 + 4] = o1;
        }
    }
}

// ---------------- host launch ----------------
extern "C" void kernel_launch(void* const* d_in, const int* in_sizes, int n_in,
                              void* d_out, int out_size) {
    const float* X   = (const float*)d_in[0];
    const int*   eiP = (const int*)d_in[1];
    const float* w   = (const float*)d_in[2];
    const float* W1  = (const float*)d_in[3];
    const float* b1  = (const float*)d_in[4];
    const float* W2  = (const float*)d_in[5];
    const float* b2  = (const float*)d_in[6];
    const float* a   = (const float*)d_in[7];
    const int*   mom = (const int*)d_in[8];

    int N = in_sizes[0] / D;
    int E = in_sizes[1] / 2;
    const int* row = eiP;
    const int* col = eiP + E;

    // resolve device scratch symbols
    float *deg, *dgcn, *dinv, *bufA, *bufB, *hbase, *W1t, *W2t;
    int *rowcnt, *rowptr, *rowcur, *bsum;
    int2 *eg, *ei;
    cudaGetSymbolAddress((void**)&deg, g_deg);
    cudaGetSymbolAddress((void**)&dgcn, g_dgcn);
    cudaGetSymbolAddress((void**)&dinv, g_dinv);
    cudaGetSymbolAddress((void**)&rowcnt, g_rowcnt);
    cudaGetSymbolAddress((void**)&rowptr, g_rowptr);
    cudaGetSymbolAddress((void**)&rowcur, g_rowcur);
    cudaGetSymbolAddress((void**)&bsum, g_bsum);
    cudaGetSymbolAddress((void**)&eg, g_eg);
    cudaGetSymbolAddress((void**)&ei, g_ei);
    cudaGetSymbolAddress((void**)&bufA, g_bufA);
    cudaGetSymbolAddress((void**)&bufB, g_bufB);
    cudaGetSymbolAddress((void**)&hbase, g_h);
    cudaGetSymbolAddress((void**)&W1t, g_W1t);
    cudaGetSymbolAddress((void**)&W2t, g_W2t);
    const long HS = (long)MAXN * D;
    float* v1 = hbase + 0 * HS;
    float* v2 = hbase + 1 * HS;
    float* v3 = hbase + 2 * HS;
    float* f1 = hbase + 3 * HS;
    float* f2 = hbase + 4 * HS;
    float* f3 = hbase + 5 * HS;
    float* f4 = bufA;
    float* hp = bufB;
    float* inter = v1;   // reuse after attn consumed it

    int nb = (N + 255) / 256;
    int eb = (E + 255) / 256;
    int wb = (N + 7) / 8;          // warp-per-row blocks (256 thr = 8 warps)

    init_kernel<<<nb, 256>>>(deg, rowcnt, N);
    deg_kernel<<<eb, 256>>>(row, col, w, deg, rowcnt, E);
    inv_kernel<<<nb, 256>>>(deg, dgcn, dinv, N);
    scanA_kernel<<<nb, 256>>>(rowcnt, bsum, N);
    scanB_kernel<<<1, 256>>>(bsum, nb);
    scanC_kernel<<<nb, 256>>>(rowcnt, bsum, rowptr, rowcur, N, E);
    build_kernel<<<eb, 256>>>(row, col, w, dgcn, dinv, rowcur, eg, ei, E);
    transpose_kernel<<<64, 256>>>(W1, W1t);
    transpose_kernel<<<64, 256>>>(W2, W2t);

    // GCN chain: raw vals v1..v3
    gcn_kernel<<<wb, 256>>>((const float4*)X,  (float4*)v1, dgcn, rowptr, eg, N);
    gcn_kernel<<<wb, 256>>>((const float4*)v1, (float4*)v2, dgcn, rowptr, eg, N);
    gcn_kernel<<<wb, 256>>>((const float4*)v2, (float4*)v3, dgcn, rowptr, eg, N);

    // Scattering chain: fp1..fp4
    scat_kernel<<<wb, 256>>>((const float4*)X,  (float4*)f1, rowptr, ei, N);
    scat_kernel<<<wb, 256>>>((const float4*)f1, (float4*)f2, rowptr, ei, N);
    scat_kernel<<<wb, 256>>>((const float4*)f2, (float4*)f3, rowptr, ei, N);
    scat_kernel<<<wb, 256>>>((const float4*)f3, (float4*)f4, rowptr, ei, N);

    // Attention -> h_prime
    attn_kernel<<<wb, 256>>>((const float4*)v1, (const float4*)v2, (const float4*)v3,
                             (const float4*)f1, (const float4*)f2, (const float4*)f3,
                             (const float4*)f4, a, mom, (float4*)hp, N);

    // Output MLP
    int gb = (N + 63) / 64;
    gemm_kernel<<<gb, 256>>>(hp, W1t, b1, inter, N);
    gemm_kernel<<<gb, 256>>>(inter, W2t, b2, (float*)d_out, N);
}